// round 14
// baseline (speedup 1.0000x reference)
#include <cuda_runtime.h>

// DimeNetBlock, round 14: software-pipelined (double-buffered) tf32 mma edge
// gather. While wave i computes from SMEM buf A, wave i+1's g_sorted + rbf
// loads are in flight into registers; STS commits to buf B after compute.
// Pipeline: hist -> lookback-scan -> permute(+self-loop list)
//           -> edge_gather -> fixup -> node.

#define NNODE 100000
#define NEDGE 3200000
constexpr int EMB = 64;

#define ANG_A 3.14129265f            /* pi - 3e-4: constant angle */
#define PI_HALF 1.5707963267948966f

typedef unsigned long long ull;

__device__ __align__(16) float g_S[(size_t)NNODE * 64];
__device__ int g_cnt[NNODE + 512];
__device__ int g_off[NNODE + 1];
__device__ int g_woff[NNODE];
__device__ int g_sorted[NEDGE];
__device__ unsigned int g_scanblk[256];
__device__ int g_slN;
__device__ int g_slE[256];

__device__ __forceinline__ float fsig(float x) {
    float e;
    asm("ex2.approx.f32 %0, %1;" : "=f"(e) : "f"(-1.4426950408889634f * x));
    float r;
    asm("rcp.approx.f32 %0, %1;" : "=f"(r) : "f"(1.0f + e));
    return r;
}
__device__ __forceinline__ float fsilu_tanh(float x) {
    float h = 0.5f * x, t;
    asm("tanh.approx.f32 %0, %1;" : "=f"(t) : "f"(h));
    return fmaf(h, t, h);
}

__device__ __forceinline__ ull pk2(float lo, float hi) {
    ull r; asm("mov.b64 %0, {%1, %2};" : "=l"(r) : "f"(lo), "f"(hi)); return r;
}
__device__ __forceinline__ float2 up2(ull v) {
    float2 f; asm("mov.b64 {%0, %1}, %2;" : "=f"(f.x), "=f"(f.y) : "l"(v)); return f;
}
__device__ __forceinline__ ull fma2(ull a, ull b, ull c) {
    ull d; asm("fma.rn.f32x2 %0, %1, %2, %3;" : "=l"(d) : "l"(a), "l"(b), "l"(c));
    return d;
}
__device__ __forceinline__ ull add2(ull a, ull b) {
    ull d; asm("add.rn.f32x2 %0, %1, %2;" : "=l"(d) : "l"(a), "l"(b)); return d;
}
__device__ __forceinline__ ull mul2(ull a, ull b) {
    ull d; asm("mul.rn.f32x2 %0, %1, %2;" : "=l"(d) : "l"(a), "l"(b)); return d;
}
__device__ __forceinline__ unsigned f2tf(float f) {
    unsigned r; asm("cvt.rna.tf32.f32 %0, %1;" : "=r"(r) : "f"(f)); return r;
}
__device__ __forceinline__ void mma_tf32(
    float& d0, float& d1, float& d2, float& d3,
    unsigned a0, unsigned a1, unsigned a2, unsigned a3,
    unsigned b0, unsigned b1)
{
    asm volatile(
        "mma.sync.aligned.m16n8k8.row.col.f32.tf32.tf32.f32 "
        "{%0,%1,%2,%3}, {%4,%5,%6,%7}, {%8,%9}, {%0,%1,%2,%3};\n"
        : "+f"(d0), "+f"(d1), "+f"(d2), "+f"(d3)
        : "r"(a0), "r"(a1), "r"(a2), "r"(a3), "r"(b0), "r"(b1));
}
__device__ __forceinline__ ull silu2(ull h) {
    ull hh = mul2(h, pk2(0.5f, 0.5f));
    float2 u = up2(hh);
    float t0, t1;
    asm("tanh.approx.f32 %0, %1;" : "=f"(t0) : "f"(u.x));
    asm("tanh.approx.f32 %0, %1;" : "=f"(t1) : "f"(u.y));
    return fma2(hh, pk2(t0, t1), hh);
}

// ---------------------------------------------------------------------------
// 1) histogram; also resets the self-loop list counter for this replay.
// ---------------------------------------------------------------------------
__global__ void hist_kernel(const int* __restrict__ eidx, int E) {
    if (blockIdx.x == 0 && threadIdx.x == 0) g_slN = 0;
    int e = blockIdx.x * blockDim.x + threadIdx.x;
    if (e >= E) return;
    atomicAdd(&g_cnt[eidx[e]], 1);
}

// ---------------------------------------------------------------------------
// 2) decoupled-lookback exclusive scan; zeroes g_cnt for next replay.
// ---------------------------------------------------------------------------
__global__ void __launch_bounds__(512) scan_kernel(int N, int E) {
    __shared__ int s[512];
    __shared__ int blk_prefix;
    int b = blockIdx.x, t = threadIdx.x;
    int i = b * 512 + t;
    int v = (i < N) ? g_cnt[i] : 0;
    if (i < N) g_cnt[i] = 0;
    s[t] = v;
    __syncthreads();
    for (int d = 1; d < 512; d <<= 1) {
        int add = (t >= d) ? s[t - d] : 0;
        __syncthreads();
        s[t] += add;
        __syncthreads();
    }
    int incl = s[t];
    if (t == 0) {
        unsigned total = (unsigned)s[511];
        volatile unsigned* vb = g_scanblk;
        if (b == 0) {
            vb[0] = total | 0x80000000u;
            blk_prefix = 0;
        } else {
            vb[b] = total | 0x40000000u;
            unsigned run = 0;
            int p = b - 1;
            while (true) {
                unsigned f = vb[p];
                unsigned st = f >> 30;
                if (st == 0u) continue;
                run += f & 0x3FFFFFFFu;
                if (st >= 2u) break;
                p--;
            }
            vb[b] = (run + total) | 0x80000000u;
            blk_prefix = (int)run;
        }
    }
    __syncthreads();
    int ex = blk_prefix + incl - v;
    if (i < N) {
        g_off[i]  = ex;
        g_woff[i] = ex;
        if (i == N - 1) g_off[N] = ex + v;
    }
}

// ---------------------------------------------------------------------------
// 3) permute: row-sorted edge ids; self-loops appended to g_slE; block 0
//    resets lookback flags for next replay.
// ---------------------------------------------------------------------------
__global__ void permute_kernel(const int* __restrict__ eidx, int E) {
    if (blockIdx.x == 0 && threadIdx.x < 256) g_scanblk[threadIdx.x] = 0u;
    int e = blockIdx.x * blockDim.x + threadIdx.x;
    if (e >= E) return;
    int r = eidx[e];
    int c = eidx[(size_t)E + e];
    int p = atomicAdd(&g_woff[r], 1);
    g_sorted[p] = e;
    if (r == c) {
        int q = atomicAdd(&g_slN, 1);
        if (q < 256) g_slE[q] = e;
    }
}

// ---------------------------------------------------------------------------
// 4) edge gather: pipelined tf32 mma (warp per node stream, 32-edge waves,
//    double buffer). Wave i+1's loads fly during wave i's compute.
// ---------------------------------------------------------------------------
__device__ __forceinline__ bool wave_adv(int& n, int& base, int& s1,
                                         int N, int stride) {
    base += 32;
    if (base >= s1) {
        n += stride;
        if (n >= N) return false;
        base = g_off[n];
        s1   = g_off[n + 1];
    }
    return true;
}

__device__ __forceinline__ void wave_loads(
    const float* __restrict__ rbf, int base, int s1,
    int lane, int gid, int tig, float4 pf[4])
{
    int idx = min(base + lane, max(s1 - 1, 0));
    int eid = g_sorted[idx];
#pragma unroll
    for (int r = 0; r < 4; r++) {
        int es = __shfl_sync(0xffffffffu, eid, r * 8 + gid);
        pf[r] = *(const float4*)&rbf[(size_t)es * 16 + 4 * tig];
    }
}

__global__ void __launch_bounds__(256, 3) edge_gather_kernel(
    const float* __restrict__ rbf,
    const float* __restrict__ W1, const float* __restrict__ b1, int N)
{
    __shared__ __align__(16) float tilebuf[8][2][32 * 20];
    __shared__ __align__(8) float sbias[64];
    const int lane = threadIdx.x & 31;
    const int wid  = threadIdx.x >> 5;
    const int gid  = lane >> 2;
    const int tig  = lane & 3;

    if (threadIdx.x < 64)
        sbias[threadIdx.x] =
            fmaf(ANG_A, W1[16 * 64 + threadIdx.x], b1[threadIdx.x]);

    unsigned Bf[8][2][2];
#pragma unroll
    for (int nt = 0; nt < 8; nt++) {
        int n = nt * 8 + gid;
#pragma unroll
        for (int kt = 0; kt < 2; kt++) {
            Bf[nt][kt][0] = f2tf(W1[(kt * 8 + tig) * 64 + n]);
            Bf[nt][kt][1] = f2tf(W1[(kt * 8 + tig + 4) * 64 + n]);
        }
    }
    __syncthreads();

    const int stride = gridDim.x * 8;

    // pipeline state: current wave (cn, cbase, cs1) staged in buf[curbuf];
    // prefetched wave (pn, pbase, ps1) resident in pf registers.
    int cn = blockIdx.x * 8 + wid, cbase = 0, cs1 = 0;
    bool chave = (cn < N);
    int pn = 0, pbase = 0, ps1 = 0;
    bool phave = false;
    float4 pf[4];
    int curbuf = 0;

    ull acc[8];
#pragma unroll
    for (int i = 0; i < 8; i++) acc[i] = 0ull;

    if (chave) {
        cbase = g_off[cn]; cs1 = g_off[cn + 1];
        wave_loads(rbf, cbase, cs1, lane, gid, tig, pf);
        float* tb = &tilebuf[wid][0][0];
#pragma unroll
        for (int r = 0; r < 4; r++)
            *(float4*)&tb[(r * 8 + gid) * 20 + 4 * tig] = pf[r];
        pn = cn; pbase = cbase; ps1 = cs1;
        phave = wave_adv(pn, pbase, ps1, N, stride);
        if (phave) wave_loads(rbf, pbase, ps1, lane, gid, tig, pf);
    }
    __syncwarp();

    while (chave) {
        int m = cs1 - cbase; if (m > 32) m = 32;
        bool lastwave = (cbase + 32 >= cs1);
        const float* tb = &tilebuf[wid][curbuf][0];

        int nmt = (m + 15) >> 4;     // warp-uniform
        for (int mt = 0; mt < nmt; mt++) {
            int r0 = mt * 16 + gid;
            bool p0 = (r0 < m), p1 = (r0 + 8 < m);
            unsigned a[2][4];
#pragma unroll
            for (int kt = 0; kt < 2; kt++) {
                a[kt][0] = f2tf(tb[r0       * 20 + kt * 8 + tig]);
                a[kt][1] = f2tf(tb[(r0 + 8) * 20 + kt * 8 + tig]);
                a[kt][2] = f2tf(tb[r0       * 20 + kt * 8 + tig + 4]);
                a[kt][3] = f2tf(tb[(r0 + 8) * 20 + kt * 8 + tig + 4]);
            }
#pragma unroll
            for (int nt = 0; nt < 8; nt++) {
                float d0 = 0.f, d1 = 0.f, d2 = 0.f, d3 = 0.f;
                mma_tf32(d0, d1, d2, d3,
                         a[0][0], a[0][1], a[0][2], a[0][3],
                         Bf[nt][0][0], Bf[nt][0][1]);
                mma_tf32(d0, d1, d2, d3,
                         a[1][0], a[1][1], a[1][2], a[1][3],
                         Bf[nt][1][0], Bf[nt][1][1]);
                ull bp = *(const ull*)&sbias[nt * 8 + 2 * tig];
                ull v0 = silu2(add2(pk2(d0, d1), bp));
                ull v1 = silu2(add2(pk2(d2, d3), bp));
                if (p0) acc[nt] = add2(acc[nt], v0);
                if (p1) acc[nt] = add2(acc[nt], v1);
            }
        }

        if (lastwave) {
#pragma unroll
            for (int nt = 0; nt < 8; nt++) {
                float2 av = up2(acc[nt]);
#pragma unroll
                for (int d = 4; d < 32; d <<= 1) {
                    av.x += __shfl_xor_sync(0xffffffffu, av.x, d);
                    av.y += __shfl_xor_sync(0xffffffffu, av.y, d);
                }
                acc[nt] = pk2(av.x, av.y);
            }
            if (gid == 0) {
#pragma unroll
                for (int nt = 0; nt < 8; nt++)
                    *(float2*)&g_S[(size_t)cn * 64 + nt * 8 + 2 * tig] =
                        up2(acc[nt]);
            }
#pragma unroll
            for (int i = 0; i < 8; i++) acc[i] = 0ull;
        }

        if (phave) {
            // commit prefetched wave, then launch loads for the wave after
            float* tb2 = &tilebuf[wid][curbuf ^ 1][0];
#pragma unroll
            for (int r = 0; r < 4; r++)
                *(float4*)&tb2[(r * 8 + gid) * 20 + 4 * tig] = pf[r];
            cn = pn; cbase = pbase; cs1 = ps1; chave = true;
            phave = wave_adv(pn, pbase, ps1, N, stride);
            if (phave) wave_loads(rbf, pbase, ps1, lane, gid, tig, pf);
            curbuf ^= 1;
        } else {
            chave = false;
        }
        __syncwarp();
    }
}

// ---------------------------------------------------------------------------
// 4b) self-loop fixup (rare).
// ---------------------------------------------------------------------------
__global__ void fixup_kernel(
    const float* __restrict__ rbf, const int* __restrict__ eidx,
    const float* __restrict__ W1, const float* __restrict__ b1, int E)
{
    int nsl = min(g_slN, 256);
    int w = threadIdx.x >> 5, lane = threadIdx.x & 31;
    for (int i = blockIdx.x * 8 + w; i < nsl; i += gridDim.x * 8) {
        int e = g_slE[i];
        int r = eidx[e];
        int c0 = 2 * lane, c1 = 2 * lane + 1;
        float h0 = b1[c0], h1 = b1[c1];
        for (int k = 0; k < 16; k++) {
            float f = rbf[(size_t)e * 16 + k];
            h0 = fmaf(f, W1[k * 64 + c0], h0);
            h1 = fmaf(f, W1[k * 64 + c1], h1);
        }
        float wa = W1[16 * 64 + c0], wb = W1[16 * 64 + c1];
        float d0 = fsilu_tanh(fmaf(PI_HALF, wa, h0)) -
                   fsilu_tanh(fmaf(ANG_A,  wa, h0));
        float d1 = fsilu_tanh(fmaf(PI_HALF, wb, h1)) -
                   fsilu_tanh(fmaf(ANG_A,  wb, h1));
        atomicAdd(&g_S[(size_t)r * 64 + c0], d0);
        atomicAdd(&g_S[(size_t)r * 64 + c1], d1);
    }
}

// ---------------------------------------------------------------------------
// 5) node: warp processes 8 nodes; 48KB weights in SMEM (unchanged).
// ---------------------------------------------------------------------------
__global__ void __launch_bounds__(256) node_kernel(
    const float* __restrict__ x,
    const float* __restrict__ W2, const float* __restrict__ b2,
    const float* __restrict__ W3, const float* __restrict__ b3,
    const float* __restrict__ W4, const float* __restrict__ b4,
    float* __restrict__ out, int N)
{
    __shared__ __align__(16) float Ws[3 * 64 * 64];
    for (int i = threadIdx.x; i < 4096; i += 256) {
        Ws[i]        = W2[i];
        Ws[4096 + i] = W3[i];
        Ws[8192 + i] = W4[i];
    }
    __syncthreads();

    int lane = threadIdx.x & 31;
    int wid  = threadIdx.x >> 5;
    float2 bb2 = *(const float2*)&b2[2 * lane];
    float2 bb3 = *(const float2*)&b3[2 * lane];
    float2 bb4 = *(const float2*)&b4[2 * lane];

    for (int g = blockIdx.x * 8 + wid; g * 8 < N; g += gridDim.x * 8) {
        int n0 = g * 8;
        float2 v[8];
        float  dg[8];
#pragma unroll
        for (int t = 0; t < 8; t++) {
            int n = n0 + t;
            if (n < N) {
                v[t]  = *(const float2*)&g_S[(size_t)n * 64 + 2 * lane];
                dg[t] = (float)(g_off[n + 1] - g_off[n]);
            } else {
                v[t] = make_float2(0.f, 0.f); dg[t] = 0.f;
            }
        }

        float2 a[8];
#pragma unroll
        for (int t = 0; t < 8; t++)
            a[t] = make_float2(dg[t] * bb2.x, dg[t] * bb2.y);

#pragma unroll 4
        for (int kk = 0; kk < 32; kk++) {
            float2 w0 = *(const float2*)&Ws[(2 * kk)     * 64 + 2 * lane];
            float2 w1 = *(const float2*)&Ws[(2 * kk + 1) * 64 + 2 * lane];
#pragma unroll
            for (int t = 0; t < 8; t++) {
                float x0 = __shfl_sync(0xffffffffu, v[t].x, kk);
                float x1 = __shfl_sync(0xffffffffu, v[t].y, kk);
                a[t].x = fmaf(x0, w0.x, fmaf(x1, w1.x, a[t].x));
                a[t].y = fmaf(x0, w0.y, fmaf(x1, w1.y, a[t].y));
            }
        }

        float2 p[8];
#pragma unroll
        for (int t = 0; t < 8; t++) p[t] = bb3;
#pragma unroll 4
        for (int kk = 0; kk < 32; kk++) {
            float2 w0 = *(const float2*)&Ws[4096 + (2 * kk)     * 64 + 2 * lane];
            float2 w1 = *(const float2*)&Ws[4096 + (2 * kk + 1) * 64 + 2 * lane];
#pragma unroll
            for (int t = 0; t < 8; t++) {
                float x0 = __shfl_sync(0xffffffffu, a[t].x, kk);
                float x1 = __shfl_sync(0xffffffffu, a[t].y, kk);
                p[t].x = fmaf(x0, w0.x, fmaf(x1, w1.x, p[t].x));
                p[t].y = fmaf(x0, w0.y, fmaf(x1, w1.y, p[t].y));
            }
        }
#pragma unroll
        for (int t = 0; t < 8; t++) {
            p[t].x *= fsig(p[t].x);
            p[t].y *= fsig(p[t].y);
        }

        float2 q[8];
#pragma unroll
        for (int t = 0; t < 8; t++) q[t] = bb4;
#pragma unroll 4
        for (int kk = 0; kk < 32; kk++) {
            float2 w0 = *(const float2*)&Ws[8192 + (2 * kk)     * 64 + 2 * lane];
            float2 w1 = *(const float2*)&Ws[8192 + (2 * kk + 1) * 64 + 2 * lane];
#pragma unroll
            for (int t = 0; t < 8; t++) {
                float x0 = __shfl_sync(0xffffffffu, p[t].x, kk);
                float x1 = __shfl_sync(0xffffffffu, p[t].y, kk);
                q[t].x = fmaf(x0, w0.x, fmaf(x1, w1.x, q[t].x));
                q[t].y = fmaf(x0, w0.y, fmaf(x1, w1.y, q[t].y));
            }
        }
#pragma unroll
        for (int t = 0; t < 8; t++) {
            int n = n0 + t;
            if (n < N) {
                float2 xv = *(const float2*)&x[(size_t)n * 64 + 2 * lane];
                *(float2*)&out[(size_t)n * 64 + 2 * lane] =
                    make_float2(xv.x + q[t].x, xv.y + q[t].y);
            }
        }
    }
}

// ---------------------------------------------------------------------------
extern "C" void kernel_launch(void* const* d_in, const int* in_sizes, int n_in,
                              void* d_out, int out_size)
{
    const float* x   = (const float*)d_in[0];
    const float* rbf = (const float*)d_in[2];
    const int*   eidx = (const int*)d_in[3];
    const float* W1 = (const float*)d_in[4];
    const float* b1 = (const float*)d_in[5];
    const float* W2 = (const float*)d_in[6];
    const float* b2 = (const float*)d_in[7];
    const float* W3 = (const float*)d_in[8];
    const float* b3 = (const float*)d_in[9];
    const float* W4 = (const float*)d_in[10];
    const float* b4 = (const float*)d_in[11];
    float* out = (float*)d_out;

    int E = in_sizes[3] / 2;
    int N = in_sizes[0] / EMB;
    int nblk = (N + 511) / 512;

    hist_kernel<<<(E + 255) / 256, 256>>>(eidx, E);
    scan_kernel<<<nblk, 512>>>(N, E);
    permute_kernel<<<(E + 255) / 256, 256>>>(eidx, E);
    edge_gather_kernel<<<592, 256>>>(rbf, W1, b1, N);
    fixup_kernel<<<4, 256>>>(rbf, eidx, W1, b1, E);
    node_kernel<<<592, 256>>>(x, W2, b2, W3, b3, W4, b4, out, N);
}

// round 15
// speedup vs baseline: 1.3308x; 1.3308x over previous
#include <cuda_runtime.h>

// DimeNetBlock, round 15: R13 edge structure + feature materialization.
// permute copies rbf[e] -> g_feat[p] (coalesced read, scattered 64B write),
// so edge_gather reads features fully coalesced/streaming: no g_sorted, no
// shfl, no random gather in the latency-critical kernel.
// Pipeline: hist -> lookback-scan -> permute(materialize) -> edge_gather
//           -> fixup -> node.

#define NNODE 100000
#define NEDGE 3200000
constexpr int EMB = 64;

#define ANG_A 3.14129265f            /* pi - 3e-4: constant angle */
#define PI_HALF 1.5707963267948966f

typedef unsigned long long ull;

__device__ __align__(16) float g_S[(size_t)NNODE * 64];
__device__ __align__(16) float g_feat[(size_t)NEDGE * 16];   // row-sorted features
__device__ int g_cnt[NNODE + 512];
__device__ int g_off[NNODE + 1];
__device__ int g_woff[NNODE];
__device__ unsigned int g_scanblk[256];
__device__ int g_slN;
__device__ int g_slE[256];

__device__ __forceinline__ float fsig(float x) {
    float e;
    asm("ex2.approx.f32 %0, %1;" : "=f"(e) : "f"(-1.4426950408889634f * x));
    float r;
    asm("rcp.approx.f32 %0, %1;" : "=f"(r) : "f"(1.0f + e));
    return r;
}
__device__ __forceinline__ float fsilu_tanh(float x) {
    float h = 0.5f * x, t;
    asm("tanh.approx.f32 %0, %1;" : "=f"(t) : "f"(h));
    return fmaf(h, t, h);
}

__device__ __forceinline__ ull pk2(float lo, float hi) {
    ull r; asm("mov.b64 %0, {%1, %2};" : "=l"(r) : "f"(lo), "f"(hi)); return r;
}
__device__ __forceinline__ float2 up2(ull v) {
    float2 f; asm("mov.b64 {%0, %1}, %2;" : "=f"(f.x), "=f"(f.y) : "l"(v)); return f;
}
__device__ __forceinline__ ull add2(ull a, ull b) {
    ull d; asm("add.rn.f32x2 %0, %1, %2;" : "=l"(d) : "l"(a), "l"(b)); return d;
}
__device__ __forceinline__ ull mul2(ull a, ull b) {
    ull d; asm("mul.rn.f32x2 %0, %1, %2;" : "=l"(d) : "l"(a), "l"(b)); return d;
}
__device__ __forceinline__ ull fma2(ull a, ull b, ull c) {
    ull d; asm("fma.rn.f32x2 %0, %1, %2, %3;" : "=l"(d) : "l"(a), "l"(b), "l"(c));
    return d;
}
__device__ __forceinline__ unsigned f2tf(float f) {
    unsigned r; asm("cvt.rna.tf32.f32 %0, %1;" : "=r"(r) : "f"(f)); return r;
}
__device__ __forceinline__ void mma_tf32(
    float& d0, float& d1, float& d2, float& d3,
    unsigned a0, unsigned a1, unsigned a2, unsigned a3,
    unsigned b0, unsigned b1)
{
    asm volatile(
        "mma.sync.aligned.m16n8k8.row.col.f32.tf32.tf32.f32 "
        "{%0,%1,%2,%3}, {%4,%5,%6,%7}, {%8,%9}, {%0,%1,%2,%3};\n"
        : "+f"(d0), "+f"(d1), "+f"(d2), "+f"(d3)
        : "r"(a0), "r"(a1), "r"(a2), "r"(a3), "r"(b0), "r"(b1));
}
__device__ __forceinline__ ull silu2(ull h) {
    ull hh = mul2(h, pk2(0.5f, 0.5f));
    float2 u = up2(hh);
    float t0, t1;
    asm("tanh.approx.f32 %0, %1;" : "=f"(t0) : "f"(u.x));
    asm("tanh.approx.f32 %0, %1;" : "=f"(t1) : "f"(u.y));
    return fma2(hh, pk2(t0, t1), hh);
}

// ---------------------------------------------------------------------------
// 1) histogram; also resets the self-loop list counter for this replay.
// ---------------------------------------------------------------------------
__global__ void hist_kernel(const int* __restrict__ eidx, int E) {
    if (blockIdx.x == 0 && threadIdx.x == 0) g_slN = 0;
    int e = blockIdx.x * blockDim.x + threadIdx.x;
    if (e >= E) return;
    atomicAdd(&g_cnt[eidx[e]], 1);
}

// ---------------------------------------------------------------------------
// 2) decoupled-lookback exclusive scan; zeroes g_cnt for next replay.
// ---------------------------------------------------------------------------
__global__ void __launch_bounds__(512) scan_kernel(int N, int E) {
    __shared__ int s[512];
    __shared__ int blk_prefix;
    int b = blockIdx.x, t = threadIdx.x;
    int i = b * 512 + t;
    int v = (i < N) ? g_cnt[i] : 0;
    if (i < N) g_cnt[i] = 0;
    s[t] = v;
    __syncthreads();
    for (int d = 1; d < 512; d <<= 1) {
        int add = (t >= d) ? s[t - d] : 0;
        __syncthreads();
        s[t] += add;
        __syncthreads();
    }
    int incl = s[t];
    if (t == 0) {
        unsigned total = (unsigned)s[511];
        volatile unsigned* vb = g_scanblk;
        if (b == 0) {
            vb[0] = total | 0x80000000u;
            blk_prefix = 0;
        } else {
            vb[b] = total | 0x40000000u;
            unsigned run = 0;
            int p = b - 1;
            while (true) {
                unsigned f = vb[p];
                unsigned st = f >> 30;
                if (st == 0u) continue;
                run += f & 0x3FFFFFFFu;
                if (st >= 2u) break;
                p--;
            }
            vb[b] = (run + total) | 0x80000000u;
            blk_prefix = (int)run;
        }
    }
    __syncthreads();
    int ex = blk_prefix + incl - v;
    if (i < N) {
        g_off[i]  = ex;
        g_woff[i] = ex;
        if (i == N - 1) g_off[N] = ex + v;
    }
}

// ---------------------------------------------------------------------------
// 3) permute + materialize: copy rbf[e] (coalesced read) into g_feat[p]
//    (scattered 64B write). Self-loops appended to g_slE. Block 0 resets
//    lookback flags for next replay.
// ---------------------------------------------------------------------------
__global__ void permute_kernel(const int* __restrict__ eidx,
                               const float* __restrict__ rbf, int E) {
    if (blockIdx.x == 0 && threadIdx.x < 256) g_scanblk[threadIdx.x] = 0u;
    int e = blockIdx.x * blockDim.x + threadIdx.x;
    if (e >= E) return;
    int r = eidx[e];
    int c = eidx[(size_t)E + e];
    int p = atomicAdd(&g_woff[r], 1);
    const float4* src = (const float4*)&rbf[(size_t)e * 16];
    float4* dst = (float4*)&g_feat[(size_t)p * 16];
    float4 f0 = src[0], f1 = src[1], f2 = src[2], f3 = src[3];
    dst[0] = f0; dst[1] = f1; dst[2] = f2; dst[3] = f3;
    if (r == c) {
        int q = atomicAdd(&g_slN, 1);
        if (q < 256) g_slE[q] = e;
    }
}

// ---------------------------------------------------------------------------
// 4) edge gather via tf32 mma (warp per node, 64-edge waves). Features read
//    COALESCED + STREAMING from g_feat — no index indirection, no shfl.
// ---------------------------------------------------------------------------
__global__ void __launch_bounds__(256, 3) edge_gather_kernel(
    const float* __restrict__ W1, const float* __restrict__ b1,
    int N, int E)
{
    __shared__ __align__(16) float tilebuf[8][64 * 20];
    __shared__ __align__(8) float sbias[64];
    const int lane = threadIdx.x & 31;
    const int wid  = threadIdx.x >> 5;
    const int gid  = lane >> 2;
    const int tig  = lane & 3;
    float* tf = tilebuf[wid];
    const float4* feat4 = (const float4*)g_feat;
    const long long E4m1 = (long long)E * 4 - 1;

    if (threadIdx.x < 64)
        sbias[threadIdx.x] =
            fmaf(ANG_A, W1[16 * 64 + threadIdx.x], b1[threadIdx.x]);

    unsigned Bf[8][2][2];
#pragma unroll
    for (int nt = 0; nt < 8; nt++) {
        int n = nt * 8 + gid;
#pragma unroll
        for (int kt = 0; kt < 2; kt++) {
            Bf[nt][kt][0] = f2tf(W1[(kt * 8 + tig) * 64 + n]);
            Bf[nt][kt][1] = f2tf(W1[(kt * 8 + tig + 4) * 64 + n]);
        }
    }
    __syncthreads();

    for (int n = blockIdx.x * 8 + wid; n < N; n += gridDim.x * 8) {
        int s0 = g_off[n], s1 = g_off[n + 1];
        ull acc[8];
#pragma unroll
        for (int i = 0; i < 8; i++) acc[i] = 0ull;

        for (int base = s0; base < s1; base += 64) {
            int m = min(64, s1 - base);

            // stage 64 edges x 16 floats = 256 float4, coalesced:
            // iter r: lane loads float4 #(r*32+lane); col=r*8+gid, kg=tig.
            long long b4 = (long long)base * 4;
#pragma unroll
            for (int r = 0; r < 8; r++) {
                long long idx = b4 + r * 32 + lane;
                float4 f4 = feat4[idx > E4m1 ? E4m1 : idx];
                *(float4*)&tf[(r * 8 + gid) * 20 + 4 * tig] = f4;
            }
            __syncwarp();

            int nmt = (m + 15) >> 4;     // warp-uniform tile count
            for (int mt = 0; mt < nmt; mt++) {
                int r0 = mt * 16 + gid;
                bool p0 = (r0 < m), p1 = (r0 + 8 < m);
                unsigned a[2][4];
#pragma unroll
                for (int kt = 0; kt < 2; kt++) {
                    a[kt][0] = f2tf(tf[r0       * 20 + kt * 8 + tig]);
                    a[kt][1] = f2tf(tf[(r0 + 8) * 20 + kt * 8 + tig]);
                    a[kt][2] = f2tf(tf[r0       * 20 + kt * 8 + tig + 4]);
                    a[kt][3] = f2tf(tf[(r0 + 8) * 20 + kt * 8 + tig + 4]);
                }
#pragma unroll
                for (int nt = 0; nt < 8; nt++) {
                    float d0 = 0.f, d1 = 0.f, d2 = 0.f, d3 = 0.f;
                    mma_tf32(d0, d1, d2, d3,
                             a[0][0], a[0][1], a[0][2], a[0][3],
                             Bf[nt][0][0], Bf[nt][0][1]);
                    mma_tf32(d0, d1, d2, d3,
                             a[1][0], a[1][1], a[1][2], a[1][3],
                             Bf[nt][1][0], Bf[nt][1][1]);
                    ull bp = *(const ull*)&sbias[nt * 8 + 2 * tig];
                    ull v0 = silu2(add2(pk2(d0, d1), bp));
                    ull v1 = silu2(add2(pk2(d2, d3), bp));
                    if (p0) acc[nt] = add2(acc[nt], v0);
                    if (p1) acc[nt] = add2(acc[nt], v1);
                }
            }
            __syncwarp();
        }

#pragma unroll
        for (int nt = 0; nt < 8; nt++) {
            float2 av = up2(acc[nt]);
#pragma unroll
            for (int d = 4; d < 32; d <<= 1) {
                av.x += __shfl_xor_sync(0xffffffffu, av.x, d);
                av.y += __shfl_xor_sync(0xffffffffu, av.y, d);
            }
            acc[nt] = pk2(av.x, av.y);
        }
        if (gid == 0) {
#pragma unroll
            for (int nt = 0; nt < 8; nt++)
                *(float2*)&g_S[(size_t)n * 64 + nt * 8 + 2 * tig] = up2(acc[nt]);
        }
    }
}

// ---------------------------------------------------------------------------
// 4b) self-loop fixup (rare).
// ---------------------------------------------------------------------------
__global__ void fixup_kernel(
    const float* __restrict__ rbf, const int* __restrict__ eidx,
    const float* __restrict__ W1, const float* __restrict__ b1, int E)
{
    int nsl = min(g_slN, 256);
    int w = threadIdx.x >> 5, lane = threadIdx.x & 31;
    for (int i = blockIdx.x * 8 + w; i < nsl; i += gridDim.x * 8) {
        int e = g_slE[i];
        int r = eidx[e];
        int c0 = 2 * lane, c1 = 2 * lane + 1;
        float h0 = b1[c0], h1 = b1[c1];
        for (int k = 0; k < 16; k++) {
            float f = rbf[(size_t)e * 16 + k];
            h0 = fmaf(f, W1[k * 64 + c0], h0);
            h1 = fmaf(f, W1[k * 64 + c1], h1);
        }
        float wa = W1[16 * 64 + c0], wb = W1[16 * 64 + c1];
        float d0 = fsilu_tanh(fmaf(PI_HALF, wa, h0)) -
                   fsilu_tanh(fmaf(ANG_A,  wa, h0));
        float d1 = fsilu_tanh(fmaf(PI_HALF, wb, h1)) -
                   fsilu_tanh(fmaf(ANG_A,  wb, h1));
        atomicAdd(&g_S[(size_t)r * 64 + c0], d0);
        atomicAdd(&g_S[(size_t)r * 64 + c1], d1);
    }
}

// ---------------------------------------------------------------------------
// 5) node: warp processes 8 nodes; 48KB weights in SMEM.
// ---------------------------------------------------------------------------
__global__ void __launch_bounds__(256) node_kernel(
    const float* __restrict__ x,
    const float* __restrict__ W2, const float* __restrict__ b2,
    const float* __restrict__ W3, const float* __restrict__ b3,
    const float* __restrict__ W4, const float* __restrict__ b4,
    float* __restrict__ out, int N)
{
    __shared__ __align__(16) float Ws[3 * 64 * 64];
    for (int i = threadIdx.x; i < 4096; i += 256) {
        Ws[i]        = W2[i];
        Ws[4096 + i] = W3[i];
        Ws[8192 + i] = W4[i];
    }
    __syncthreads();

    int lane = threadIdx.x & 31;
    int wid  = threadIdx.x >> 5;
    float2 bb2 = *(const float2*)&b2[2 * lane];
    float2 bb3 = *(const float2*)&b3[2 * lane];
    float2 bb4 = *(const float2*)&b4[2 * lane];

    for (int g = blockIdx.x * 8 + wid; g * 8 < N; g += gridDim.x * 8) {
        int n0 = g * 8;
        float2 v[8];
        float  dg[8];
#pragma unroll
        for (int t = 0; t < 8; t++) {
            int n = n0 + t;
            if (n < N) {
                v[t]  = *(const float2*)&g_S[(size_t)n * 64 + 2 * lane];
                dg[t] = (float)(g_off[n + 1] - g_off[n]);
            } else {
                v[t] = make_float2(0.f, 0.f); dg[t] = 0.f;
            }
        }

        float2 a[8];
#pragma unroll
        for (int t = 0; t < 8; t++)
            a[t] = make_float2(dg[t] * bb2.x, dg[t] * bb2.y);

#pragma unroll 4
        for (int kk = 0; kk < 32; kk++) {
            float2 w0 = *(const float2*)&Ws[(2 * kk)     * 64 + 2 * lane];
            float2 w1 = *(const float2*)&Ws[(2 * kk + 1) * 64 + 2 * lane];
#pragma unroll
            for (int t = 0; t < 8; t++) {
                float x0 = __shfl_sync(0xffffffffu, v[t].x, kk);
                float x1 = __shfl_sync(0xffffffffu, v[t].y, kk);
                a[t].x = fmaf(x0, w0.x, fmaf(x1, w1.x, a[t].x));
                a[t].y = fmaf(x0, w0.y, fmaf(x1, w1.y, a[t].y));
            }
        }

        float2 p[8];
#pragma unroll
        for (int t = 0; t < 8; t++) p[t] = bb3;
#pragma unroll 4
        for (int kk = 0; kk < 32; kk++) {
            float2 w0 = *(const float2*)&Ws[4096 + (2 * kk)     * 64 + 2 * lane];
            float2 w1 = *(const float2*)&Ws[4096 + (2 * kk + 1) * 64 + 2 * lane];
#pragma unroll
            for (int t = 0; t < 8; t++) {
                float x0 = __shfl_sync(0xffffffffu, a[t].x, kk);
                float x1 = __shfl_sync(0xffffffffu, a[t].y, kk);
                p[t].x = fmaf(x0, w0.x, fmaf(x1, w1.x, p[t].x));
                p[t].y = fmaf(x0, w0.y, fmaf(x1, w1.y, p[t].y));
            }
        }
#pragma unroll
        for (int t = 0; t < 8; t++) {
            p[t].x *= fsig(p[t].x);
            p[t].y *= fsig(p[t].y);
        }

        float2 q[8];
#pragma unroll
        for (int t = 0; t < 8; t++) q[t] = bb4;
#pragma unroll 4
        for (int kk = 0; kk < 32; kk++) {
            float2 w0 = *(const float2*)&Ws[8192 + (2 * kk)     * 64 + 2 * lane];
            float2 w1 = *(const float2*)&Ws[8192 + (2 * kk + 1) * 64 + 2 * lane];
#pragma unroll
            for (int t = 0; t < 8; t++) {
                float x0 = __shfl_sync(0xffffffffu, p[t].x, kk);
                float x1 = __shfl_sync(0xffffffffu, p[t].y, kk);
                q[t].x = fmaf(x0, w0.x, fmaf(x1, w1.x, q[t].x));
                q[t].y = fmaf(x0, w0.y, fmaf(x1, w1.y, q[t].y));
            }
        }
#pragma unroll
        for (int t = 0; t < 8; t++) {
            int n = n0 + t;
            if (n < N) {
                float2 xv = *(const float2*)&x[(size_t)n * 64 + 2 * lane];
                *(float2*)&out[(size_t)n * 64 + 2 * lane] =
                    make_float2(xv.x + q[t].x, xv.y + q[t].y);
            }
        }
    }
}

// ---------------------------------------------------------------------------
extern "C" void kernel_launch(void* const* d_in, const int* in_sizes, int n_in,
                              void* d_out, int out_size)
{
    const float* x   = (const float*)d_in[0];
    const float* rbf = (const float*)d_in[2];
    const int*   eidx = (const int*)d_in[3];
    const float* W1 = (const float*)d_in[4];
    const float* b1 = (const float*)d_in[5];
    const float* W2 = (const float*)d_in[6];
    const float* b2 = (const float*)d_in[7];
    const float* W3 = (const float*)d_in[8];
    const float* b3 = (const float*)d_in[9];
    const float* W4 = (const float*)d_in[10];
    const float* b4 = (const float*)d_in[11];
    float* out = (float*)d_out;

    int E = in_sizes[3] / 2;
    int N = in_sizes[0] / EMB;
    int nblk = (N + 511) / 512;

    hist_kernel<<<(E + 255) / 256, 256>>>(eidx, E);
    scan_kernel<<<nblk, 512>>>(N, E);
    permute_kernel<<<(E + 255) / 256, 256>>>(eidx, rbf, E);
    edge_gather_kernel<<<592, 256>>>(W1, b1, N, E);
    fixup_kernel<<<4, 256>>>(rbf, eidx, W1, b1, E);
    node_kernel<<<592, 256>>>(x, W2, b2, W3, b3, W4, b4, out, N);
}

// round 16
// speedup vs baseline: 1.4831x; 1.1144x over previous
#include <cuda_runtime.h>

// DimeNetBlock, round 16: R13 pipeline (best total) + two fixes:
//  - edge grid 444 = 3 resident blocks x 148 SMs (was 592 -> straggler wave)
//  - node kernel matvecs in packed fma.rn.f32x2 (halves FMA issue)
// Pipeline: hist -> lookback-scan -> permute -> edge_gather -> fixup -> node.

#define NNODE 100000
#define NEDGE 3200000
constexpr int EMB = 64;

#define ANG_A 3.14129265f            /* pi - 3e-4: constant angle */
#define PI_HALF 1.5707963267948966f

typedef unsigned long long ull;

__device__ __align__(16) float g_S[(size_t)NNODE * 64];
__device__ int g_cnt[NNODE + 512];
__device__ int g_off[NNODE + 1];
__device__ int g_woff[NNODE];
__device__ int g_sorted[NEDGE];
__device__ unsigned int g_scanblk[256];
__device__ int g_slN;
__device__ int g_slE[256];

__device__ __forceinline__ float fsig(float x) {
    float e;
    asm("ex2.approx.f32 %0, %1;" : "=f"(e) : "f"(-1.4426950408889634f * x));
    float r;
    asm("rcp.approx.f32 %0, %1;" : "=f"(r) : "f"(1.0f + e));
    return r;
}
__device__ __forceinline__ float fsilu_tanh(float x) {
    float h = 0.5f * x, t;
    asm("tanh.approx.f32 %0, %1;" : "=f"(t) : "f"(h));
    return fmaf(h, t, h);
}

__device__ __forceinline__ ull pk2(float lo, float hi) {
    ull r; asm("mov.b64 %0, {%1, %2};" : "=l"(r) : "f"(lo), "f"(hi)); return r;
}
__device__ __forceinline__ float2 up2(ull v) {
    float2 f; asm("mov.b64 {%0, %1}, %2;" : "=f"(f.x), "=f"(f.y) : "l"(v)); return f;
}
__device__ __forceinline__ ull fma2(ull a, ull b, ull c) {
    ull d; asm("fma.rn.f32x2 %0, %1, %2, %3;" : "=l"(d) : "l"(a), "l"(b), "l"(c));
    return d;
}
__device__ __forceinline__ ull add2(ull a, ull b) {
    ull d; asm("add.rn.f32x2 %0, %1, %2;" : "=l"(d) : "l"(a), "l"(b)); return d;
}
__device__ __forceinline__ ull mul2(ull a, ull b) {
    ull d; asm("mul.rn.f32x2 %0, %1, %2;" : "=l"(d) : "l"(a), "l"(b)); return d;
}
__device__ __forceinline__ unsigned f2tf(float f) {
    unsigned r; asm("cvt.rna.tf32.f32 %0, %1;" : "=r"(r) : "f"(f)); return r;
}
__device__ __forceinline__ void mma_tf32(
    float& d0, float& d1, float& d2, float& d3,
    unsigned a0, unsigned a1, unsigned a2, unsigned a3,
    unsigned b0, unsigned b1)
{
    asm volatile(
        "mma.sync.aligned.m16n8k8.row.col.f32.tf32.tf32.f32 "
        "{%0,%1,%2,%3}, {%4,%5,%6,%7}, {%8,%9}, {%0,%1,%2,%3};\n"
        : "+f"(d0), "+f"(d1), "+f"(d2), "+f"(d3)
        : "r"(a0), "r"(a1), "r"(a2), "r"(a3), "r"(b0), "r"(b1));
}
__device__ __forceinline__ ull silu2(ull h) {
    ull hh = mul2(h, pk2(0.5f, 0.5f));
    float2 u = up2(hh);
    float t0, t1;
    asm("tanh.approx.f32 %0, %1;" : "=f"(t0) : "f"(u.x));
    asm("tanh.approx.f32 %0, %1;" : "=f"(t1) : "f"(u.y));
    return fma2(hh, pk2(t0, t1), hh);
}

// ---------------------------------------------------------------------------
// 1) histogram; also resets the self-loop list counter for this replay.
// ---------------------------------------------------------------------------
__global__ void hist_kernel(const int* __restrict__ eidx, int E) {
    if (blockIdx.x == 0 && threadIdx.x == 0) g_slN = 0;
    int e = blockIdx.x * blockDim.x + threadIdx.x;
    if (e >= E) return;
    atomicAdd(&g_cnt[eidx[e]], 1);
}

// ---------------------------------------------------------------------------
// 2) decoupled-lookback exclusive scan; zeroes g_cnt for next replay.
// ---------------------------------------------------------------------------
__global__ void __launch_bounds__(512) scan_kernel(int N, int E) {
    __shared__ int s[512];
    __shared__ int blk_prefix;
    int b = blockIdx.x, t = threadIdx.x;
    int i = b * 512 + t;
    int v = (i < N) ? g_cnt[i] : 0;
    if (i < N) g_cnt[i] = 0;
    s[t] = v;
    __syncthreads();
    for (int d = 1; d < 512; d <<= 1) {
        int add = (t >= d) ? s[t - d] : 0;
        __syncthreads();
        s[t] += add;
        __syncthreads();
    }
    int incl = s[t];
    if (t == 0) {
        unsigned total = (unsigned)s[511];
        volatile unsigned* vb = g_scanblk;
        if (b == 0) {
            vb[0] = total | 0x80000000u;
            blk_prefix = 0;
        } else {
            vb[b] = total | 0x40000000u;
            unsigned run = 0;
            int p = b - 1;
            while (true) {
                unsigned f = vb[p];
                unsigned st = f >> 30;
                if (st == 0u) continue;
                run += f & 0x3FFFFFFFu;
                if (st >= 2u) break;
                p--;
            }
            vb[b] = (run + total) | 0x80000000u;
            blk_prefix = (int)run;
        }
    }
    __syncthreads();
    int ex = blk_prefix + incl - v;
    if (i < N) {
        g_off[i]  = ex;
        g_woff[i] = ex;
        if (i == N - 1) g_off[N] = ex + v;
    }
}

// ---------------------------------------------------------------------------
// 3) permute: row-sorted edge ids; self-loops appended to g_slE; block 0
//    resets lookback flags for next replay.
// ---------------------------------------------------------------------------
__global__ void permute_kernel(const int* __restrict__ eidx, int E) {
    if (blockIdx.x == 0 && threadIdx.x < 256) g_scanblk[threadIdx.x] = 0u;
    int e = blockIdx.x * blockDim.x + threadIdx.x;
    if (e >= E) return;
    int r = eidx[e];
    int c = eidx[(size_t)E + e];
    int p = atomicAdd(&g_woff[r], 1);
    g_sorted[p] = e;
    if (r == c) {
        int q = atomicAdd(&g_slN, 1);
        if (q < 256) g_slE[q] = e;
    }
}

// ---------------------------------------------------------------------------
// 4) edge gather via tf32 mma.sync (warp per node), 64-edge staging waves.
//    Launched with 444 blocks = 3 resident/SM x 148 SMs (one balanced wave).
// ---------------------------------------------------------------------------
__global__ void __launch_bounds__(256, 3) edge_gather_kernel(
    const float* __restrict__ rbf,
    const float* __restrict__ W1, const float* __restrict__ b1, int N)
{
    __shared__ __align__(16) float tilebuf[8][64 * 20];
    __shared__ __align__(8) float sbias[64];
    const int lane = threadIdx.x & 31;
    const int wid  = threadIdx.x >> 5;
    const int gid  = lane >> 2;
    const int tig  = lane & 3;
    float* tf = tilebuf[wid];

    if (threadIdx.x < 64)
        sbias[threadIdx.x] =
            fmaf(ANG_A, W1[16 * 64 + threadIdx.x], b1[threadIdx.x]);

    unsigned Bf[8][2][2];
#pragma unroll
    for (int nt = 0; nt < 8; nt++) {
        int n = nt * 8 + gid;
#pragma unroll
        for (int kt = 0; kt < 2; kt++) {
            Bf[nt][kt][0] = f2tf(W1[(kt * 8 + tig) * 64 + n]);
            Bf[nt][kt][1] = f2tf(W1[(kt * 8 + tig + 4) * 64 + n]);
        }
    }
    __syncthreads();

    for (int n = blockIdx.x * 8 + wid; n < N; n += gridDim.x * 8) {
        int s0 = g_off[n], s1 = g_off[n + 1];
        ull acc[8];
#pragma unroll
        for (int i = 0; i < 8; i++) acc[i] = 0ull;

        for (int base = s0; base < s1; base += 64) {
            int m = min(64, s1 - base);
            int eA = g_sorted[min(base + lane,      s1 - 1)];
            int eB = g_sorted[min(base + 32 + lane, s1 - 1)];

#pragma unroll
            for (int r = 0; r < 4; r++) {
                int col = r * 8 + gid;
                int es = __shfl_sync(0xffffffffu, eA, col);
                float4 f4 = *(const float4*)&rbf[(size_t)es * 16 + 4 * tig];
                *(float4*)&tf[col * 20 + 4 * tig] = f4;
            }
#pragma unroll
            for (int r = 4; r < 8; r++) {
                int col = r * 8 + gid;
                int es = __shfl_sync(0xffffffffu, eB, col - 32);
                float4 f4 = *(const float4*)&rbf[(size_t)es * 16 + 4 * tig];
                *(float4*)&tf[col * 20 + 4 * tig] = f4;
            }
            __syncwarp();

            int nmt = (m + 15) >> 4;     // warp-uniform tile count
            for (int mt = 0; mt < nmt; mt++) {
                int r0 = mt * 16 + gid;
                bool p0 = (r0 < m), p1 = (r0 + 8 < m);
                unsigned a[2][4];
#pragma unroll
                for (int kt = 0; kt < 2; kt++) {
                    a[kt][0] = f2tf(tf[r0       * 20 + kt * 8 + tig]);
                    a[kt][1] = f2tf(tf[(r0 + 8) * 20 + kt * 8 + tig]);
                    a[kt][2] = f2tf(tf[r0       * 20 + kt * 8 + tig + 4]);
                    a[kt][3] = f2tf(tf[(r0 + 8) * 20 + kt * 8 + tig + 4]);
                }
#pragma unroll
                for (int nt = 0; nt < 8; nt++) {
                    float d0 = 0.f, d1 = 0.f, d2 = 0.f, d3 = 0.f;
                    mma_tf32(d0, d1, d2, d3,
                             a[0][0], a[0][1], a[0][2], a[0][3],
                             Bf[nt][0][0], Bf[nt][0][1]);
                    mma_tf32(d0, d1, d2, d3,
                             a[1][0], a[1][1], a[1][2], a[1][3],
                             Bf[nt][1][0], Bf[nt][1][1]);
                    ull bp = *(const ull*)&sbias[nt * 8 + 2 * tig];
                    ull v0 = silu2(add2(pk2(d0, d1), bp));
                    ull v1 = silu2(add2(pk2(d2, d3), bp));
                    if (p0) acc[nt] = add2(acc[nt], v0);
                    if (p1) acc[nt] = add2(acc[nt], v1);
                }
            }
            __syncwarp();
        }

#pragma unroll
        for (int nt = 0; nt < 8; nt++) {
            float2 av = up2(acc[nt]);
#pragma unroll
            for (int d = 4; d < 32; d <<= 1) {
                av.x += __shfl_xor_sync(0xffffffffu, av.x, d);
                av.y += __shfl_xor_sync(0xffffffffu, av.y, d);
            }
            acc[nt] = pk2(av.x, av.y);
        }
        if (gid == 0) {
#pragma unroll
            for (int nt = 0; nt < 8; nt++)
                *(float2*)&g_S[(size_t)n * 64 + nt * 8 + 2 * tig] = up2(acc[nt]);
        }
    }
}

// ---------------------------------------------------------------------------
// 4b) self-loop fixup (rare).
// ---------------------------------------------------------------------------
__global__ void fixup_kernel(
    const float* __restrict__ rbf, const int* __restrict__ eidx,
    const float* __restrict__ W1, const float* __restrict__ b1, int E)
{
    int nsl = min(g_slN, 256);
    int w = threadIdx.x >> 5, lane = threadIdx.x & 31;
    for (int i = blockIdx.x * 8 + w; i < nsl; i += gridDim.x * 8) {
        int e = g_slE[i];
        int r = eidx[e];
        int c0 = 2 * lane, c1 = 2 * lane + 1;
        float h0 = b1[c0], h1 = b1[c1];
        for (int k = 0; k < 16; k++) {
            float f = rbf[(size_t)e * 16 + k];
            h0 = fmaf(f, W1[k * 64 + c0], h0);
            h1 = fmaf(f, W1[k * 64 + c1], h1);
        }
        float wa = W1[16 * 64 + c0], wb = W1[16 * 64 + c1];
        float d0 = fsilu_tanh(fmaf(PI_HALF, wa, h0)) -
                   fsilu_tanh(fmaf(ANG_A,  wa, h0));
        float d1 = fsilu_tanh(fmaf(PI_HALF, wb, h1)) -
                   fsilu_tanh(fmaf(ANG_A,  wb, h1));
        atomicAdd(&g_S[(size_t)r * 64 + c0], d0);
        atomicAdd(&g_S[(size_t)r * 64 + c1], d1);
    }
}

// ---------------------------------------------------------------------------
// 5) node: warp processes 8 nodes; 48KB weights in SMEM; packed f32x2 math.
//    Lane owns cols (2*lane, 2*lane+1) -> accumulators are f32x2 pairs.
// ---------------------------------------------------------------------------
__global__ void __launch_bounds__(256) node_kernel(
    const float* __restrict__ x,
    const float* __restrict__ W2, const float* __restrict__ b2,
    const float* __restrict__ W3, const float* __restrict__ b3,
    const float* __restrict__ W4, const float* __restrict__ b4,
    float* __restrict__ out, int N)
{
    __shared__ __align__(16) float Ws[3 * 64 * 64];
    for (int i = threadIdx.x; i < 4096; i += 256) {
        Ws[i]        = W2[i];
        Ws[4096 + i] = W3[i];
        Ws[8192 + i] = W4[i];
    }
    __syncthreads();

    int lane = threadIdx.x & 31;
    int wid  = threadIdx.x >> 5;
    ull bb2p = *(const ull*)&b2[2 * lane];
    ull bb3p = *(const ull*)&b3[2 * lane];
    ull bb4p = *(const ull*)&b4[2 * lane];

    for (int g = blockIdx.x * 8 + wid; g * 8 < N; g += gridDim.x * 8) {
        int n0 = g * 8;
        float2 v[8];
        float  dg[8];
#pragma unroll
        for (int t = 0; t < 8; t++) {
            int n = n0 + t;
            if (n < N) {
                v[t]  = *(const float2*)&g_S[(size_t)n * 64 + 2 * lane];
                dg[t] = (float)(g_off[n + 1] - g_off[n]);
            } else {
                v[t] = make_float2(0.f, 0.f); dg[t] = 0.f;
            }
        }

        // stage A: a = S @ W2 + deg*b2   (packed per col-pair)
        ull a2[8];
#pragma unroll
        for (int t = 0; t < 8; t++)
            a2[t] = mul2(pk2(dg[t], dg[t]), bb2p);
#pragma unroll 4
        for (int kk = 0; kk < 32; kk++) {
            ull wp0 = *(const ull*)&Ws[(2 * kk)     * 64 + 2 * lane];
            ull wp1 = *(const ull*)&Ws[(2 * kk + 1) * 64 + 2 * lane];
#pragma unroll
            for (int t = 0; t < 8; t++) {
                float x0 = __shfl_sync(0xffffffffu, v[t].x, kk);
                float x1 = __shfl_sync(0xffffffffu, v[t].y, kk);
                a2[t] = fma2(pk2(x0, x0), wp0, a2[t]);
                a2[t] = fma2(pk2(x1, x1), wp1, a2[t]);
            }
        }
        float2 av[8];
#pragma unroll
        for (int t = 0; t < 8; t++) av[t] = up2(a2[t]);

        // stage B: p = silu(a @ W3 + b3)
        ull p2[8];
#pragma unroll
        for (int t = 0; t < 8; t++) p2[t] = bb3p;
#pragma unroll 4
        for (int kk = 0; kk < 32; kk++) {
            ull wp0 = *(const ull*)&Ws[4096 + (2 * kk)     * 64 + 2 * lane];
            ull wp1 = *(const ull*)&Ws[4096 + (2 * kk + 1) * 64 + 2 * lane];
#pragma unroll
            for (int t = 0; t < 8; t++) {
                float x0 = __shfl_sync(0xffffffffu, av[t].x, kk);
                float x1 = __shfl_sync(0xffffffffu, av[t].y, kk);
                p2[t] = fma2(pk2(x0, x0), wp0, p2[t]);
                p2[t] = fma2(pk2(x1, x1), wp1, p2[t]);
            }
        }
        float2 pv[8];
#pragma unroll
        for (int t = 0; t < 8; t++) {
            float2 u = up2(p2[t]);
            u.x *= fsig(u.x);
            u.y *= fsig(u.y);
            pv[t] = u;
        }

        // stage C: q = p @ W4 + b4 ; out = x + q
        ull q2[8];
#pragma unroll
        for (int t = 0; t < 8; t++) q2[t] = bb4p;
#pragma unroll 4
        for (int kk = 0; kk < 32; kk++) {
            ull wp0 = *(const ull*)&Ws[8192 + (2 * kk)     * 64 + 2 * lane];
            ull wp1 = *(const ull*)&Ws[8192 + (2 * kk + 1) * 64 + 2 * lane];
#pragma unroll
            for (int t = 0; t < 8; t++) {
                float x0 = __shfl_sync(0xffffffffu, pv[t].x, kk);
                float x1 = __shfl_sync(0xffffffffu, pv[t].y, kk);
                q2[t] = fma2(pk2(x0, x0), wp0, q2[t]);
                q2[t] = fma2(pk2(x1, x1), wp1, q2[t]);
            }
        }
#pragma unroll
        for (int t = 0; t < 8; t++) {
            int n = n0 + t;
            if (n < N) {
                float2 xv = *(const float2*)&x[(size_t)n * 64 + 2 * lane];
                float2 qv = up2(q2[t]);
                *(float2*)&out[(size_t)n * 64 + 2 * lane] =
                    make_float2(xv.x + qv.x, xv.y + qv.y);
            }
        }
    }
}

// ---------------------------------------------------------------------------
extern "C" void kernel_launch(void* const* d_in, const int* in_sizes, int n_in,
                              void* d_out, int out_size)
{
    const float* x   = (const float*)d_in[0];
    const float* rbf = (const float*)d_in[2];
    const int*   eidx = (const int*)d_in[3];
    const float* W1 = (const float*)d_in[4];
    const float* b1 = (const float*)d_in[5];
    const float* W2 = (const float*)d_in[6];
    const float* b2 = (const float*)d_in[7];
    const float* W3 = (const float*)d_in[8];
    const float* b3 = (const float*)d_in[9];
    const float* W4 = (const float*)d_in[10];
    const float* b4 = (const float*)d_in[11];
    float* out = (float*)d_out;

    int E = in_sizes[3] / 2;
    int N = in_sizes[0] / EMB;
    int nblk = (N + 511) / 512;

    hist_kernel<<<(E + 255) / 256, 256>>>(eidx, E);
    scan_kernel<<<nblk, 512>>>(N, E);
    permute_kernel<<<(E + 255) / 256, 256>>>(eidx, E);
    edge_gather_kernel<<<444, 256>>>(rbf, W1, b1, N);   // 3 resident x 148 SM
    fixup_kernel<<<4, 256>>>(rbf, eidx, W1, b1, E);
    node_kernel<<<592, 256>>>(x, W2, b2, W3, b3, W4, b4, out, N);
}

// round 17
// speedup vs baseline: 1.6545x; 1.1155x over previous
#include <cuda_runtime.h>

// DimeNetBlock, round 17: R16 + tensor-core node kernel.
// Node: 3 chained 64x64 tf32 mma GEMM stages per 16-node warp tile; A frags
// via per-warp SMEM tile (stride 68, conflict-free), B frags from weights
// pre-converted to tf32 in hist_kernel (L1-resident), stage outputs
// transposed through the tile, epilogue adds x coalesced.
// Pipeline: hist(+wconv) -> lookback-scan -> permute -> edge_gather -> fixup
//           -> node.

#define NNODE 100000
#define NEDGE 3200000
constexpr int EMB = 64;

#define ANG_A 3.14129265f            /* pi - 3e-4: constant angle */
#define PI_HALF 1.5707963267948966f

typedef unsigned long long ull;

__device__ __align__(16) float g_S[(size_t)NNODE * 64];
__device__ int g_cnt[NNODE + 512];
__device__ int g_off[NNODE + 1];
__device__ int g_woff[NNODE];
__device__ int g_sorted[NEDGE];
__device__ unsigned int g_scanblk[256];
__device__ int g_slN;
__device__ int g_slE[256];
__device__ unsigned g_wtf[3 * 4096];      // W2,W3,W4 pre-converted to tf32

__device__ __forceinline__ float fsilu_tanh(float x) {
    float h = 0.5f * x, t;
    asm("tanh.approx.f32 %0, %1;" : "=f"(t) : "f"(h));
    return fmaf(h, t, h);
}

__device__ __forceinline__ ull pk2(float lo, float hi) {
    ull r; asm("mov.b64 %0, {%1, %2};" : "=l"(r) : "f"(lo), "f"(hi)); return r;
}
__device__ __forceinline__ float2 up2(ull v) {
    float2 f; asm("mov.b64 {%0, %1}, %2;" : "=f"(f.x), "=f"(f.y) : "l"(v)); return f;
}
__device__ __forceinline__ ull fma2(ull a, ull b, ull c) {
    ull d; asm("fma.rn.f32x2 %0, %1, %2, %3;" : "=l"(d) : "l"(a), "l"(b), "l"(c));
    return d;
}
__device__ __forceinline__ ull add2(ull a, ull b) {
    ull d; asm("add.rn.f32x2 %0, %1, %2;" : "=l"(d) : "l"(a), "l"(b)); return d;
}
__device__ __forceinline__ ull mul2(ull a, ull b) {
    ull d; asm("mul.rn.f32x2 %0, %1, %2;" : "=l"(d) : "l"(a), "l"(b)); return d;
}
__device__ __forceinline__ unsigned f2tf(float f) {
    unsigned r; asm("cvt.rna.tf32.f32 %0, %1;" : "=r"(r) : "f"(f)); return r;
}
__device__ __forceinline__ void mma_tf32(
    float& d0, float& d1, float& d2, float& d3,
    unsigned a0, unsigned a1, unsigned a2, unsigned a3,
    unsigned b0, unsigned b1)
{
    asm volatile(
        "mma.sync.aligned.m16n8k8.row.col.f32.tf32.tf32.f32 "
        "{%0,%1,%2,%3}, {%4,%5,%6,%7}, {%8,%9}, {%0,%1,%2,%3};\n"
        : "+f"(d0), "+f"(d1), "+f"(d2), "+f"(d3)
        : "r"(a0), "r"(a1), "r"(a2), "r"(a3), "r"(b0), "r"(b1));
}
__device__ __forceinline__ ull silu2(ull h) {
    ull hh = mul2(h, pk2(0.5f, 0.5f));
    float2 u = up2(hh);
    float t0, t1;
    asm("tanh.approx.f32 %0, %1;" : "=f"(t0) : "f"(u.x));
    asm("tanh.approx.f32 %0, %1;" : "=f"(t1) : "f"(u.y));
    return fma2(hh, pk2(t0, t1), hh);
}

// ---------------------------------------------------------------------------
// 1) histogram; resets self-loop counter; converts W2/3/4 to tf32.
// ---------------------------------------------------------------------------
__global__ void hist_kernel(const int* __restrict__ eidx, int E,
                            const float* __restrict__ W2,
                            const float* __restrict__ W3,
                            const float* __restrict__ W4) {
    int t = blockIdx.x * blockDim.x + threadIdx.x;
    if (t == 0) g_slN = 0;
    if (t < 3 * 4096) {
        const float* W = (t < 4096) ? W2 : ((t < 8192) ? W3 : W4);
        g_wtf[t] = f2tf(W[t & 4095]);
    }
    if (t >= E) return;
    atomicAdd(&g_cnt[eidx[t]], 1);
}

// ---------------------------------------------------------------------------
// 2) decoupled-lookback exclusive scan; zeroes g_cnt for next replay.
// ---------------------------------------------------------------------------
__global__ void __launch_bounds__(512) scan_kernel(int N, int E) {
    __shared__ int s[512];
    __shared__ int blk_prefix;
    int b = blockIdx.x, t = threadIdx.x;
    int i = b * 512 + t;
    int v = (i < N) ? g_cnt[i] : 0;
    if (i < N) g_cnt[i] = 0;
    s[t] = v;
    __syncthreads();
    for (int d = 1; d < 512; d <<= 1) {
        int add = (t >= d) ? s[t - d] : 0;
        __syncthreads();
        s[t] += add;
        __syncthreads();
    }
    int incl = s[t];
    if (t == 0) {
        unsigned total = (unsigned)s[511];
        volatile unsigned* vb = g_scanblk;
        if (b == 0) {
            vb[0] = total | 0x80000000u;
            blk_prefix = 0;
        } else {
            vb[b] = total | 0x40000000u;
            unsigned run = 0;
            int p = b - 1;
            while (true) {
                unsigned f = vb[p];
                unsigned st = f >> 30;
                if (st == 0u) continue;
                run += f & 0x3FFFFFFFu;
                if (st >= 2u) break;
                p--;
            }
            vb[b] = (run + total) | 0x80000000u;
            blk_prefix = (int)run;
        }
    }
    __syncthreads();
    int ex = blk_prefix + incl - v;
    if (i < N) {
        g_off[i]  = ex;
        g_woff[i] = ex;
        if (i == N - 1) g_off[N] = ex + v;
    }
}

// ---------------------------------------------------------------------------
// 3) permute: row-sorted edge ids; self-loops appended to g_slE; block 0
//    resets lookback flags for next replay.
// ---------------------------------------------------------------------------
__global__ void permute_kernel(const int* __restrict__ eidx, int E) {
    if (blockIdx.x == 0 && threadIdx.x < 256) g_scanblk[threadIdx.x] = 0u;
    int e = blockIdx.x * blockDim.x + threadIdx.x;
    if (e >= E) return;
    int r = eidx[e];
    int c = eidx[(size_t)E + e];
    int p = atomicAdd(&g_woff[r], 1);
    g_sorted[p] = e;
    if (r == c) {
        int q = atomicAdd(&g_slN, 1);
        if (q < 256) g_slE[q] = e;
    }
}

// ---------------------------------------------------------------------------
// 4) edge gather via tf32 mma.sync (warp per node), 64-edge staging waves.
//    444 blocks = 3 resident/SM x 148 SMs (one balanced wave).
// ---------------------------------------------------------------------------
__global__ void __launch_bounds__(256, 3) edge_gather_kernel(
    const float* __restrict__ rbf,
    const float* __restrict__ W1, const float* __restrict__ b1, int N)
{
    __shared__ __align__(16) float tilebuf[8][64 * 20];
    __shared__ __align__(8) float sbias[64];
    const int lane = threadIdx.x & 31;
    const int wid  = threadIdx.x >> 5;
    const int gid  = lane >> 2;
    const int tig  = lane & 3;
    float* tf = tilebuf[wid];

    if (threadIdx.x < 64)
        sbias[threadIdx.x] =
            fmaf(ANG_A, W1[16 * 64 + threadIdx.x], b1[threadIdx.x]);

    unsigned Bf[8][2][2];
#pragma unroll
    for (int nt = 0; nt < 8; nt++) {
        int n = nt * 8 + gid;
#pragma unroll
        for (int kt = 0; kt < 2; kt++) {
            Bf[nt][kt][0] = f2tf(W1[(kt * 8 + tig) * 64 + n]);
            Bf[nt][kt][1] = f2tf(W1[(kt * 8 + tig + 4) * 64 + n]);
        }
    }
    __syncthreads();

    for (int n = blockIdx.x * 8 + wid; n < N; n += gridDim.x * 8) {
        int s0 = g_off[n], s1 = g_off[n + 1];
        ull acc[8];
#pragma unroll
        for (int i = 0; i < 8; i++) acc[i] = 0ull;

        for (int base = s0; base < s1; base += 64) {
            int m = min(64, s1 - base);
            int eA = g_sorted[min(base + lane,      s1 - 1)];
            int eB = g_sorted[min(base + 32 + lane, s1 - 1)];

#pragma unroll
            for (int r = 0; r < 4; r++) {
                int col = r * 8 + gid;
                int es = __shfl_sync(0xffffffffu, eA, col);
                float4 f4 = *(const float4*)&rbf[(size_t)es * 16 + 4 * tig];
                *(float4*)&tf[col * 20 + 4 * tig] = f4;
            }
#pragma unroll
            for (int r = 4; r < 8; r++) {
                int col = r * 8 + gid;
                int es = __shfl_sync(0xffffffffu, eB, col - 32);
                float4 f4 = *(const float4*)&rbf[(size_t)es * 16 + 4 * tig];
                *(float4*)&tf[col * 20 + 4 * tig] = f4;
            }
            __syncwarp();

            int nmt = (m + 15) >> 4;
            for (int mt = 0; mt < nmt; mt++) {
                int r0 = mt * 16 + gid;
                bool p0 = (r0 < m), p1 = (r0 + 8 < m);
                unsigned a[2][4];
#pragma unroll
                for (int kt = 0; kt < 2; kt++) {
                    a[kt][0] = f2tf(tf[r0       * 20 + kt * 8 + tig]);
                    a[kt][1] = f2tf(tf[(r0 + 8) * 20 + kt * 8 + tig]);
                    a[kt][2] = f2tf(tf[r0       * 20 + kt * 8 + tig + 4]);
                    a[kt][3] = f2tf(tf[(r0 + 8) * 20 + kt * 8 + tig + 4]);
                }
#pragma unroll
                for (int nt = 0; nt < 8; nt++) {
                    float d0 = 0.f, d1 = 0.f, d2 = 0.f, d3 = 0.f;
                    mma_tf32(d0, d1, d2, d3,
                             a[0][0], a[0][1], a[0][2], a[0][3],
                             Bf[nt][0][0], Bf[nt][0][1]);
                    mma_tf32(d0, d1, d2, d3,
                             a[1][0], a[1][1], a[1][2], a[1][3],
                             Bf[nt][1][0], Bf[nt][1][1]);
                    ull bp = *(const ull*)&sbias[nt * 8 + 2 * tig];
                    ull v0 = silu2(add2(pk2(d0, d1), bp));
                    ull v1 = silu2(add2(pk2(d2, d3), bp));
                    if (p0) acc[nt] = add2(acc[nt], v0);
                    if (p1) acc[nt] = add2(acc[nt], v1);
                }
            }
            __syncwarp();
        }

#pragma unroll
        for (int nt = 0; nt < 8; nt++) {
            float2 av = up2(acc[nt]);
#pragma unroll
            for (int d = 4; d < 32; d <<= 1) {
                av.x += __shfl_xor_sync(0xffffffffu, av.x, d);
                av.y += __shfl_xor_sync(0xffffffffu, av.y, d);
            }
            acc[nt] = pk2(av.x, av.y);
        }
        if (gid == 0) {
#pragma unroll
            for (int nt = 0; nt < 8; nt++)
                *(float2*)&g_S[(size_t)n * 64 + nt * 8 + 2 * tig] = up2(acc[nt]);
        }
    }
}

// ---------------------------------------------------------------------------
// 4b) self-loop fixup (rare).
// ---------------------------------------------------------------------------
__global__ void fixup_kernel(
    const float* __restrict__ rbf, const int* __restrict__ eidx,
    const float* __restrict__ W1, const float* __restrict__ b1, int E)
{
    int nsl = min(g_slN, 256);
    int w = threadIdx.x >> 5, lane = threadIdx.x & 31;
    for (int i = blockIdx.x * 8 + w; i < nsl; i += gridDim.x * 8) {
        int e = g_slE[i];
        int r = eidx[e];
        int c0 = 2 * lane, c1 = 2 * lane + 1;
        float h0 = b1[c0], h1 = b1[c1];
        for (int k = 0; k < 16; k++) {
            float f = rbf[(size_t)e * 16 + k];
            h0 = fmaf(f, W1[k * 64 + c0], h0);
            h1 = fmaf(f, W1[k * 64 + c1], h1);
        }
        float wa = W1[16 * 64 + c0], wb = W1[16 * 64 + c1];
        float d0 = fsilu_tanh(fmaf(PI_HALF, wa, h0)) -
                   fsilu_tanh(fmaf(ANG_A,  wa, h0));
        float d1 = fsilu_tanh(fmaf(PI_HALF, wb, h1)) -
                   fsilu_tanh(fmaf(ANG_A,  wb, h1));
        atomicAdd(&g_S[(size_t)r * 64 + c0], d0);
        atomicAdd(&g_S[(size_t)r * 64 + c1], d1);
    }
}

// ---------------------------------------------------------------------------
// 5) node: tensor-core. Warp = 16-node tile; 3 chained 64x64 tf32 GEMMs with
//    transpose-through-SMEM between stages; weights from g_wtf (L1).
// ---------------------------------------------------------------------------
__global__ void __launch_bounds__(256) node_kernel(
    const float* __restrict__ x,
    const float* __restrict__ b2, const float* __restrict__ b3,
    const float* __restrict__ b4,
    float* __restrict__ out, int N)
{
    __shared__ __align__(16) float tiles[8][16 * 68];
    __shared__ __align__(8) float sbias[3 * 64];
    if (threadIdx.x < 64) {
        sbias[threadIdx.x]       = b2[threadIdx.x];
        sbias[64 + threadIdx.x]  = b3[threadIdx.x];
        sbias[128 + threadIdx.x] = b4[threadIdx.x];
    }
    __syncthreads();

    const int lane = threadIdx.x & 31;
    const int wid  = threadIdx.x >> 5;
    const int gid  = lane >> 2;
    const int tig  = lane & 3;
    float* tf = tiles[wid];

    for (int tile = blockIdx.x * 8 + wid; tile * 16 < N;
         tile += gridDim.x * 8) {
        int nb = tile * 16;
        // stage S rows 16x64 coalesced
#pragma unroll
        for (int r = 0; r < 8; r++) {
            int idx = r * 32 + lane;
            int row = idx >> 4, c4 = idx & 15;
            int n = min(nb + row, N - 1);
            float4 v = *(const float4*)&g_S[(size_t)n * 64 + 4 * c4];
            *(float4*)&tf[row * 68 + 4 * c4] = v;
        }
        int nlo = min(nb + gid, N - 1), nhi = min(nb + gid + 8, N - 1);
        float dgl = (float)(g_off[nlo + 1] - g_off[nlo]);
        float dgh = (float)(g_off[nhi + 1] - g_off[nhi]);
        __syncwarp();

        float acc[8][4];
#pragma unroll
        for (int s = 0; s < 3; s++) {
#pragma unroll
            for (int nt = 0; nt < 8; nt++) {
                float2 bb = *(const float2*)&sbias[s * 64 + nt * 8 + 2 * tig];
                if (s == 0) {
                    acc[nt][0] = dgl * bb.x; acc[nt][1] = dgl * bb.y;
                    acc[nt][2] = dgh * bb.x; acc[nt][3] = dgh * bb.y;
                } else {
                    acc[nt][0] = bb.x; acc[nt][1] = bb.y;
                    acc[nt][2] = bb.x; acc[nt][3] = bb.y;
                }
            }
            const unsigned* Ws = &g_wtf[s * 4096];
#pragma unroll
            for (int kt = 0; kt < 8; kt++) {
                unsigned a0 = f2tf(tf[gid * 68 + kt * 8 + tig]);
                unsigned a1 = f2tf(tf[(gid + 8) * 68 + kt * 8 + tig]);
                unsigned a2 = f2tf(tf[gid * 68 + kt * 8 + tig + 4]);
                unsigned a3 = f2tf(tf[(gid + 8) * 68 + kt * 8 + tig + 4]);
#pragma unroll
                for (int nt = 0; nt < 8; nt++) {
                    unsigned b0 = __ldg(&Ws[(kt * 8 + tig) * 64 + nt * 8 + gid]);
                    unsigned b1 = __ldg(&Ws[(kt * 8 + tig + 4) * 64 + nt * 8 + gid]);
                    mma_tf32(acc[nt][0], acc[nt][1], acc[nt][2], acc[nt][3],
                             a0, a1, a2, a3, b0, b1);
                }
            }
            if (s == 1) {
#pragma unroll
                for (int nt = 0; nt < 8; nt++)
#pragma unroll
                    for (int j = 0; j < 4; j++)
                        acc[nt][j] = fsilu_tanh(acc[nt][j]);
            }
            __syncwarp();
#pragma unroll
            for (int nt = 0; nt < 8; nt++) {
                *(float2*)&tf[gid * 68 + nt * 8 + 2 * tig] =
                    make_float2(acc[nt][0], acc[nt][1]);
                *(float2*)&tf[(gid + 8) * 68 + nt * 8 + 2 * tig] =
                    make_float2(acc[nt][2], acc[nt][3]);
            }
            __syncwarp();
        }
        // epilogue: out = x + q (coalesced)
#pragma unroll
        for (int r = 0; r < 8; r++) {
            int idx = r * 32 + lane;
            int row = idx >> 4, c4 = idx & 15;
            int n = nb + row;
            if (n < N) {
                float4 xv = *(const float4*)&x[(size_t)n * 64 + 4 * c4];
                float4 qv = *(const float4*)&tf[row * 68 + 4 * c4];
                *(float4*)&out[(size_t)n * 64 + 4 * c4] = make_float4(
                    xv.x + qv.x, xv.y + qv.y, xv.z + qv.z, xv.w + qv.w);
            }
        }
        __syncwarp();
    }
}

// ---------------------------------------------------------------------------
extern "C" void kernel_launch(void* const* d_in, const int* in_sizes, int n_in,
                              void* d_out, int out_size)
{
    const float* x   = (const float*)d_in[0];
    const float* rbf = (const float*)d_in[2];
    const int*   eidx = (const int*)d_in[3];
    const float* W1 = (const float*)d_in[4];
    const float* b1 = (const float*)d_in[5];
    const float* W2 = (const float*)d_in[6];
    const float* b2 = (const float*)d_in[7];
    const float* W3 = (const float*)d_in[8];
    const float* b3 = (const float*)d_in[9];
    const float* W4 = (const float*)d_in[10];
    const float* b4 = (const float*)d_in[11];
    float* out = (float*)d_out;

    int E = in_sizes[3] / 2;
    int N = in_sizes[0] / EMB;
    int nblk = (N + 511) / 512;

    hist_kernel<<<(E + 255) / 256, 256>>>(eidx, E, W2, W3, W4);
    scan_kernel<<<nblk, 512>>>(N, E);
    permute_kernel<<<(E + 255) / 256, 256>>>(eidx, E);
    edge_gather_kernel<<<444, 256>>>(rbf, W1, b1, N);
    fixup_kernel<<<4, 256>>>(rbf, eidx, W1, b1, E);
    node_kernel<<<444, 256>>>(x, b2, b3, b4, out, N);
}